// round 4
// baseline (speedup 1.0000x reference)
#include <cuda_runtime.h>
#include <math.h>

#define BATCH 4
#define PP 900
#define DM 512
#define HH 8
#define DK 64
#define SIDE 30
#define C1 32
#define P2 810000
#define MP (BATCH*PP)

// fused conv tiling
#define WT 450          // conv2 output w per tile
#define NTILE 2
#define SROWS 50        // conv2 output rows per strip
#define NSTRIP 18
#define RW 456          // ring row width (conv1 w range 452, padded)
#define NCHUNK1 113     // conv1 4-wide chunks (452/4)
#define RING_BYTES (3*32*RW*4)              // 175104
#define WSM1_BYTES (8*9*16*8)               // 9216
#define WSM2_BYTES (32*9*4*8)               // 9216
#define FUSED_SMEM (RING_BYTES + WSM1_BYTES + WSM2_BYTES + 128)

typedef unsigned long long u64;

__device__ __forceinline__ u64 pack2(float a, float b) {
    u64 r; asm("mov.b64 %0, {%1,%2};" : "=l"(r) : "f"(a), "f"(b)); return r;
}
__device__ __forceinline__ u64 ffma2(u64 a, u64 b, u64 c) {
    u64 d; asm("fma.rn.f32x2 %0, %1, %2, %3;" : "=l"(d) : "l"(a), "l"(b), "l"(c)); return d;
}
__device__ __forceinline__ float2 unpack2(u64 v) {
    float2 f; asm("mov.b64 {%0,%1}, %2;" : "=f"(f.x), "=f"(f.y) : "l"(v)); return f;
}

__device__ __align__(128) float g_q[MP * DM];
__device__ __align__(128) float g_k[MP * DM];
__device__ __align__(128) float g_scores[BATCH * HH * P2];
__device__ __align__(128) int   g_idx[BATCH * HH * PP];
__device__ __align__(128) float g_part[NTILE][BATCH * PP];

// ---------------- projection GEMM: C = A @ W^T + bias ----------------------
__global__ __launch_bounds__(256) void proj_gemm_kernel(
    const float* __restrict__ A, const float* __restrict__ Wm,
    const float* __restrict__ bias, int which)
{
    float* C = which ? g_k : g_q;
    __shared__ __align__(16) float As[16][132];
    __shared__ __align__(16) float Bs[16][132];
    const int t  = threadIdx.x;
    const int m0 = blockIdx.y * 128;
    const int n0 = blockIdx.x * 128;
    const int lr = t >> 2;
    const int lc = (t & 3) << 2;
    const int ty = t >> 4, tx = t & 15;
    u64 acc[8][4];
    #pragma unroll
    for (int i = 0; i < 8; i++)
        #pragma unroll
        for (int j = 0; j < 4; j++) acc[i][j] = 0ull;

    for (int k0 = 0; k0 < DM; k0 += 16) {
        int ar0 = m0 + lr, ar1 = m0 + lr + 64;
        float4 a0 = make_float4(0.f,0.f,0.f,0.f), a1 = a0;
        if (ar0 < MP) a0 = *(const float4*)(A + (size_t)ar0 * DM + k0 + lc);
        if (ar1 < MP) a1 = *(const float4*)(A + (size_t)ar1 * DM + k0 + lc);
        float4 b0 = *(const float4*)(Wm + (size_t)(n0 + lr)      * DM + k0 + lc);
        float4 b1 = *(const float4*)(Wm + (size_t)(n0 + lr + 64) * DM + k0 + lc);
        if (k0) __syncthreads();
        As[lc+0][lr] = a0.x; As[lc+1][lr] = a0.y; As[lc+2][lr] = a0.z; As[lc+3][lr] = a0.w;
        As[lc+0][lr+64] = a1.x; As[lc+1][lr+64] = a1.y; As[lc+2][lr+64] = a1.z; As[lc+3][lr+64] = a1.w;
        Bs[lc+0][lr] = b0.x; Bs[lc+1][lr] = b0.y; Bs[lc+2][lr] = b0.z; Bs[lc+3][lr] = b0.w;
        Bs[lc+0][lr+64] = b1.x; Bs[lc+1][lr+64] = b1.y; Bs[lc+2][lr+64] = b1.z; Bs[lc+3][lr+64] = b1.w;
        __syncthreads();
        #pragma unroll
        for (int kk = 0; kk < 16; kk++) {
            float a[8];
            *(float4*)&a[0] = *(const float4*)&As[kk][ty*8];
            *(float4*)&a[4] = *(const float4*)&As[kk][ty*8+4];
            ulonglong2 B0 = *(const ulonglong2*)&Bs[kk][tx*8];
            ulonglong2 B1 = *(const ulonglong2*)&Bs[kk][tx*8+4];
            #pragma unroll
            for (int i = 0; i < 8; i++) {
                u64 aa = pack2(a[i], a[i]);
                acc[i][0] = ffma2(aa, B0.x, acc[i][0]);
                acc[i][1] = ffma2(aa, B0.y, acc[i][1]);
                acc[i][2] = ffma2(aa, B1.x, acc[i][2]);
                acc[i][3] = ffma2(aa, B1.y, acc[i][3]);
            }
        }
    }
    const int c0 = n0 + tx * 8;
    float bi[8];
    #pragma unroll
    for (int j = 0; j < 8; j++) bi[j] = bias[c0 + j];
    #pragma unroll
    for (int i = 0; i < 8; i++) {
        int r = m0 + ty * 8 + i;
        if (r >= MP) continue;
        float* cp = C + (size_t)r * DM + c0;
        #pragma unroll
        for (int j = 0; j < 4; j++) {
            float2 f = unpack2(acc[i][j]);
            cp[j*2+0] = f.x + bi[j*2+0];
            cp[j*2+1] = f.y + bi[j*2+1];
        }
    }
}

// ---------------- batched scores GEMM: scores[b,h] = Qh @ Kh^T -------------
__global__ __launch_bounds__(256) void scores_gemm_kernel()
{
    const int z = blockIdx.z;
    const int b = z >> 3, h = z & 7;
    const float* A  = g_q + (size_t)b * PP * DM + h * DK;
    const float* Bm = g_k + (size_t)b * PP * DM + h * DK;
    float* C = g_scores + (size_t)z * P2;

    __shared__ __align__(16) float As[16][132];
    __shared__ __align__(16) float Bs[16][132];
    const int t  = threadIdx.x;
    const int m0 = blockIdx.y * 128;
    const int n0 = blockIdx.x * 128;
    const int lr = t >> 2;
    const int lc = (t & 3) << 2;
    const int ty = t >> 4, tx = t & 15;
    u64 acc[8][4];
    #pragma unroll
    for (int i = 0; i < 8; i++)
        #pragma unroll
        for (int j = 0; j < 4; j++) acc[i][j] = 0ull;

    for (int k0 = 0; k0 < DK; k0 += 16) {
        int ar0 = m0 + lr, ar1 = m0 + lr + 64;
        int br0 = n0 + lr, br1 = n0 + lr + 64;
        float4 a0 = make_float4(0.f,0.f,0.f,0.f), a1 = a0, b0 = a0, b1 = a0;
        if (ar0 < PP) a0 = *(const float4*)(A  + (size_t)ar0 * DM + k0 + lc);
        if (ar1 < PP) a1 = *(const float4*)(A  + (size_t)ar1 * DM + k0 + lc);
        if (br0 < PP) b0 = *(const float4*)(Bm + (size_t)br0 * DM + k0 + lc);
        if (br1 < PP) b1 = *(const float4*)(Bm + (size_t)br1 * DM + k0 + lc);
        if (k0) __syncthreads();
        As[lc+0][lr] = a0.x; As[lc+1][lr] = a0.y; As[lc+2][lr] = a0.z; As[lc+3][lr] = a0.w;
        As[lc+0][lr+64] = a1.x; As[lc+1][lr+64] = a1.y; As[lc+2][lr+64] = a1.z; As[lc+3][lr+64] = a1.w;
        Bs[lc+0][lr] = b0.x; Bs[lc+1][lr] = b0.y; Bs[lc+2][lr] = b0.z; Bs[lc+3][lr] = b0.w;
        Bs[lc+0][lr+64] = b1.x; Bs[lc+1][lr+64] = b1.y; Bs[lc+2][lr+64] = b1.z; Bs[lc+3][lr+64] = b1.w;
        __syncthreads();
        #pragma unroll
        for (int kk = 0; kk < 16; kk++) {
            float a[8];
            *(float4*)&a[0] = *(const float4*)&As[kk][ty*8];
            *(float4*)&a[4] = *(const float4*)&As[kk][ty*8+4];
            ulonglong2 B0 = *(const ulonglong2*)&Bs[kk][tx*8];
            ulonglong2 B1 = *(const ulonglong2*)&Bs[kk][tx*8+4];
            #pragma unroll
            for (int i = 0; i < 8; i++) {
                u64 aa = pack2(a[i], a[i]);
                acc[i][0] = ffma2(aa, B0.x, acc[i][0]);
                acc[i][1] = ffma2(aa, B0.y, acc[i][1]);
                acc[i][2] = ffma2(aa, B1.x, acc[i][2]);
                acc[i][3] = ffma2(aa, B1.y, acc[i][3]);
            }
        }
    }
    const int c0 = n0 + tx * 8;
    #pragma unroll
    for (int i = 0; i < 8; i++) {
        int r = m0 + ty * 8 + i;
        if (r >= PP) continue;
        float* cp = C + (size_t)r * PP;
        #pragma unroll
        for (int j = 0; j < 4; j++) {
            float2 f = unpack2(acc[i][j]);
            int c = c0 + j * 2;
            if (c     < PP) cp[c]     = f.x;
            if (c + 1 < PP) cp[c + 1] = f.y;
        }
    }
}

// ---------------- column argmax over p for each (bh, w) --------------------
__global__ __launch_bounds__(256) void argmax_kernel()
{
    const int w  = blockIdx.x * 256 + threadIdx.x;
    const int bh = blockIdx.y;
    if (w >= PP) return;
    const float* base = g_scores + (size_t)bh * P2 + w;
    float best = base[0];
    int   bi = 0;
    int p = 1;
    for (; p + 15 < PP; p += 16) {
        float v[16];
        #pragma unroll
        for (int u = 0; u < 16; u++) v[u] = base[(size_t)(p + u) * PP];
        #pragma unroll
        for (int u = 0; u < 16; u++)
            if (v[u] > best) { best = v[u]; bi = p + u; }
    }
    for (; p < PP; p++) {
        float v = base[(size_t)p * PP];
        if (v > best) { best = v; bi = p; }
    }
    g_idx[bh * PP + w] = bi;
}

// ---------------- gaussian modulation + scale + softmax (in-place) ---------
__global__ __launch_bounds__(256) void gauss_softmax_kernel()
{
    const int p  = blockIdx.x;
    const int bh = blockIdx.y;
    float* row = g_scores + ((size_t)bh * PP + p) * PP;
    const int* idxr = g_idx + bh * PP;
    const int t = threadIdx.x;
    const float ys0 = -1.0f + (2.0f / 29.0f) * (float)(p / SIDE);
    const float xs0 = -1.0f + (2.0f / 29.0f) * (float)(p % SIDE);

    __shared__ float sh[32];
    float v[4];
    float m = -3.0e38f;
    #pragma unroll
    for (int i = 0; i < 4; i++) {
        int w = t + i * 256;
        v[i] = -3.0e38f;
        if (w < PP) {
            int id = idxr[w];
            int iy = id / SIDE;
            float fy = (float)iy;
            float fx = (float)(id - iy * SIDE);
            float ddx = xs0 - fx;
            float ddy = ys0 - fy;
            float g = expf(-(ddx * ddx + ddy * ddy) * (1.0f / 50.0f));
            v[i] = g * row[w] * 0.125f;
            m = fmaxf(m, v[i]);
        }
    }
    #pragma unroll
    for (int off = 16; off; off >>= 1) m = fmaxf(m, __shfl_xor_sync(0xffffffffu, m, off));
    if ((t & 31) == 0) sh[t >> 5] = m;
    __syncthreads();
    if (t < 32) {
        float x = (t < 8) ? sh[t] : -3.0e38f;
        #pragma unroll
        for (int off = 4; off; off >>= 1) x = fmaxf(x, __shfl_xor_sync(0xffffffffu, x, off));
        if (t == 0) sh[0] = x;
    }
    __syncthreads();
    m = sh[0];
    __syncthreads();

    float e[4];
    float s = 0.f;
    #pragma unroll
    for (int i = 0; i < 4; i++) {
        int w = t + i * 256;
        e[i] = 0.f;
        if (w < PP) { e[i] = expf(v[i] - m); s += e[i]; }
    }
    #pragma unroll
    for (int off = 16; off; off >>= 1) s += __shfl_xor_sync(0xffffffffu, s, off);
    if ((t & 31) == 0) sh[t >> 5] = s;
    __syncthreads();
    if (t < 32) {
        float x = (t < 8) ? sh[t] : 0.f;
        #pragma unroll
        for (int off = 4; off; off >>= 1) x += __shfl_xor_sync(0xffffffffu, x, off);
        if (t == 0) sh[0] = x;
    }
    __syncthreads();
    float inv = 1.0f / sh[0];
    #pragma unroll
    for (int i = 0; i < 4; i++) {
        int w = t + i * 256;
        if (w < PP) row[w] = e[i] * inv;
    }
}

// =================== fused conv1 + conv2 + value-dot =======================
// Block = (tile, strip, b). Ring buffer of 3 conv1 rows in smem.
// conv1 row r: 32ch x [w0-1, w0+450] (452 w, chunks of 4, 113 chunks)
// conv2 row p: 8oc x [w0, w0+449], thread = 2 contiguous w, all 32 ci.
__device__ __forceinline__ void conv1_row_compute(
    const float* __restrict__ attn, int w0, int r,
    int ocg, int slot, int tid, const u64* bia,
    float* __restrict__ ring, const u64* __restrict__ wsm1)
{
    const int s3 = ((r % 3) + 3) % 3;
    float* rslot = ring + (size_t)s3 * 32 * RW;
    if (r < 0 || r >= PP) {
        for (int i = tid; i < 32 * RW; i += 256) rslot[i] = 0.f;
        return;
    }
    #pragma unroll 1
    for (int j = 0; j < 2; j++) {
        const int c = j * 64 + slot;
        if (c >= NCHUNK1) continue;
        const int x0 = w0 - 2 + 4 * c;
        u64 acc[4][4];
        #pragma unroll
        for (int k = 0; k < 4; k++)
            #pragma unroll
            for (int op = 0; op < 4; op++) acc[k][op] = bia[op];

        #pragma unroll 1
        for (int ci = 0; ci < 8; ci++) {
            #pragma unroll
            for (int dy = 0; dy < 3; dy++) {
                int rr = r + dy - 1;
                if (rr < 0 || rr >= PP) continue;
                const float* rp = attn + (size_t)ci * P2 + (size_t)rr * PP;
                float v[6];
                #pragma unroll
                for (int m = 0; m < 6; m++) {
                    int x = x0 + m;
                    v[m] = (x >= 0 && x < PP) ? rp[x] : 0.f;
                }
                u64 in2[6];
                #pragma unroll
                for (int m = 0; m < 6; m++) in2[m] = pack2(v[m], v[m]);
                const u64* wb = wsm1 + (ci * 9 + dy * 3) * 16 + ocg * 4;
                #pragma unroll
                for (int dx = 0; dx < 3; dx++) {
                    u64 wp0 = wb[dx * 16 + 0];
                    u64 wp1 = wb[dx * 16 + 1];
                    u64 wp2 = wb[dx * 16 + 2];
                    u64 wp3 = wb[dx * 16 + 3];
                    #pragma unroll
                    for (int k = 0; k < 4; k++) {
                        acc[k][0] = ffma2(in2[k + dx], wp0, acc[k][0]);
                        acc[k][1] = ffma2(in2[k + dx], wp1, acc[k][1]);
                        acc[k][2] = ffma2(in2[k + dx], wp2, acc[k][2]);
                        acc[k][3] = ffma2(in2[k + dx], wp3, acc[k][3]);
                    }
                }
            }
        }
        // validity per k: global conv1 w = w0 - 1 + 4c + k must be in [0, PP)
        bool mk[4];
        #pragma unroll
        for (int k = 0; k < 4; k++) {
            int wg = w0 - 1 + 4 * c + k;
            mk[k] = (wg >= 0 && wg < PP);
        }
        float* base0 = rslot + (size_t)(ocg * 8) * RW + 4 * c;
        #pragma unroll
        for (int op = 0; op < 4; op++) {
            float2 f0 = unpack2(acc[0][op]);
            float2 f1 = unpack2(acc[1][op]);
            float2 f2 = unpack2(acc[2][op]);
            float2 f3 = unpack2(acc[3][op]);
            float4 A = make_float4(mk[0] ? fmaxf(f0.x, 0.f) : 0.f,
                                   mk[1] ? fmaxf(f1.x, 0.f) : 0.f,
                                   mk[2] ? fmaxf(f2.x, 0.f) : 0.f,
                                   mk[3] ? fmaxf(f3.x, 0.f) : 0.f);
            float4 Bv = make_float4(mk[0] ? fmaxf(f0.y, 0.f) : 0.f,
                                    mk[1] ? fmaxf(f1.y, 0.f) : 0.f,
                                    mk[2] ? fmaxf(f2.y, 0.f) : 0.f,
                                    mk[3] ? fmaxf(f3.y, 0.f) : 0.f);
            *(float4*)(base0 + (size_t)(2 * op) * RW)     = A;
            *(float4*)(base0 + (size_t)(2 * op + 1) * RW) = Bv;
        }
    }
}

__global__ __launch_bounds__(256, 1) void fused_conv_kernel(
    const float* __restrict__ w1, const float* __restrict__ b1,
    const float* __restrict__ w2, const float* __restrict__ b2,
    const float* __restrict__ value)
{
    extern __shared__ unsigned char smraw[];
    float* ring = (float*)smraw;                                   // [3][32][RW]
    u64*   wsm1 = (u64*)(smraw + RING_BYTES);                      // [8*9*16]
    u64*   wsm2 = (u64*)(smraw + RING_BYTES + WSM1_BYTES);         // [32*9*4]
    float* shred = (float*)(smraw + RING_BYTES + WSM1_BYTES + WSM2_BYTES); // [32]

    const int tid  = threadIdx.x;
    const int tile = blockIdx.x & 1;
    const int strip = blockIdx.x >> 1;
    const int bb   = blockIdx.y;
    const int w0   = tile * WT;
    const int p0s  = strip * SROWS;
    const int ocg  = tid >> 6;
    const int slot = tid & 63;

    // load packed weights
    for (int i = tid; i < 8 * 9 * 16; i += 256) {
        int op  = i & 3;
        int og  = (i >> 2) & 3;
        int rest = i >> 4;
        int ci  = rest / 9;
        int dydx = rest - ci * 9;
        int oc0 = og * 8 + op * 2;
        wsm1[i] = pack2(w1[(oc0 * 8 + ci) * 9 + dydx],
                        w1[((oc0 + 1) * 8 + ci) * 9 + dydx]);
    }
    for (int i = tid; i < 32 * 9 * 4; i += 256) {
        int op = i & 3;
        int rest = i >> 2;
        int ci = rest / 9;
        int dydx = rest - ci * 9;
        wsm2[i] = pack2(w2[(op * 2 * 32 + ci) * 9 + dydx],
                        w2[((op * 2 + 1) * 32 + ci) * 9 + dydx]);
    }
    __syncthreads();

    const float* attn = g_scores + (size_t)bb * HH * P2;

    u64 bia1[4];
    #pragma unroll
    for (int op = 0; op < 4; op++)
        bia1[op] = pack2(b1[ocg * 8 + op * 2], b1[ocg * 8 + op * 2 + 1]);
    u64 bia2[4];
    #pragma unroll
    for (int op = 0; op < 4; op++)
        bia2[op] = pack2(b2[op * 2], b2[op * 2 + 1]);

    // prologue: conv1 rows p0s-1 and p0s
    conv1_row_compute(attn, w0, p0s - 1, ocg, slot, tid, bia1, ring, wsm1);
    conv1_row_compute(attn, w0, p0s,     ocg, slot, tid, bia1, ring, wsm1);
    __syncthreads();

    const int  c2     = tid;
    const bool active = (c2 < 225);

    #pragma unroll 1
    for (int p = p0s; p < p0s + SROWS; p++) {
        // produce conv1 row p+1
        conv1_row_compute(attn, w0, p + 1, ocg, slot, tid, bia1, ring, wsm1);
        __syncthreads();

        // conv2 row p (thread: 2 contiguous w, all 32 ci, 8 oc)
        float part = 0.f;
        if (active) {
            u64 acc[2][4];
            #pragma unroll
            for (int k = 0; k < 2; k++)
                #pragma unroll
                for (int op = 0; op < 4; op++) acc[k][op] = bia2[op];

            const int sm = (p + 2) % 3;   // row p-1
            const int s0 = p % 3;         // row p
            const int sp = (p + 1) % 3;   // row p+1
            const int rs[3] = {sm, s0, sp};

            #pragma unroll 1
            for (int ci = 0; ci < C1; ci++) {
                #pragma unroll
                for (int dy = 0; dy < 3; dy++) {
                    const float* rg = ring + ((size_t)rs[dy] * 32 + ci) * RW + 2 * c2;
                    float2 va = *(const float2*)rg;
                    float2 vb = *(const float2*)(rg + 2);
                    u64 in2[4];
                    in2[0] = pack2(va.x, va.x);
                    in2[1] = pack2(va.y, va.y);
                    in2[2] = pack2(vb.x, vb.x);
                    in2[3] = pack2(vb.y, vb.y);
                    const u64* wb = wsm2 + (ci * 9 + dy * 3) * 4;
                    #pragma unroll
                    for (int dx = 0; dx < 3; dx++) {
                        u64 p0 = wb[dx * 4 + 0];
                        u64 p1 = wb[dx * 4 + 1];
                        u64 p2 = wb[dx * 4 + 2];
                        u64 p3 = wb[dx * 4 + 3];
                        #pragma unroll
                        for (int k = 0; k < 2; k++) {
                            acc[k][0] = ffma2(in2[k + dx], p0, acc[k][0]);
                            acc[k][1] = ffma2(in2[k + dx], p1, acc[k][1]);
                            acc[k][2] = ffma2(in2[k + dx], p2, acc[k][2]);
                            acc[k][3] = ffma2(in2[k + dx], p3, acc[k][3]);
                        }
                    }
                }
            }
            // relu + value dot (sum over 8 oc)
            #pragma unroll
            for (int k = 0; k < 2; k++) {
                int wg = w0 + 2 * c2 + k;
                float val = value[bb * PP + wg];
                float s = 0.f;
                #pragma unroll
                for (int op = 0; op < 4; op++) {
                    float2 f = unpack2(acc[k][op]);
                    s += fmaxf(f.x, 0.f) + fmaxf(f.y, 0.f);
                }
                part += s * val;
            }
        }
        // block reduce
        #pragma unroll
        for (int off = 16; off; off >>= 1)
            part += __shfl_xor_sync(0xffffffffu, part, off);
        if ((tid & 31) == 0) shred[tid >> 5] = part;
        __syncthreads();
        if (tid < 32) {
            float x = (tid < 8) ? shred[tid] : 0.f;
            #pragma unroll
            for (int off = 4; off; off >>= 1)
                x += __shfl_xor_sync(0xffffffffu, x, off);
            if (tid == 0) g_part[tile][bb * PP + p] = x;
        }
        __syncthreads();
    }
}

// final combine: out = mean over heads of (tile partials)
__global__ void combine_kernel(float* __restrict__ out)
{
    int i = blockIdx.x * 256 + threadIdx.x;
    if (i < BATCH * PP)
        out[i] = 0.125f * (g_part[0][i] + g_part[1][i]);
}

// ---------------------------------------------------------------------------
extern "C" void kernel_launch(void* const* d_in, const int* in_sizes, int n_in,
                              void* d_out, int out_size)
{
    const float* query = (const float*)d_in[0];
    const float* key_t = (const float*)d_in[1];
    const float* value = (const float*)d_in[2];
    const float* Wq    = (const float*)d_in[3];
    const float* bq    = (const float*)d_in[4];
    const float* Wk    = (const float*)d_in[5];
    const float* bk    = (const float*)d_in[6];
    const float* c1w   = (const float*)d_in[7];
    const float* c1b   = (const float*)d_in[8];
    const float* c2w   = (const float*)d_in[9];
    const float* c2b   = (const float*)d_in[10];
    float* out = (float*)d_out;
    (void)in_sizes; (void)n_in; (void)out_size;

    proj_gemm_kernel<<<dim3(4, 29), 256>>>(query, Wq, bq, 0);
    proj_gemm_kernel<<<dim3(4, 29), 256>>>(key_t, Wk, bk, 1);
    scores_gemm_kernel<<<dim3(8, 8, 32), 256>>>();
    argmax_kernel<<<dim3(4, 32), 256>>>();
    gauss_softmax_kernel<<<dim3(900, 32), 256>>>();

    cudaFuncSetAttribute(fused_conv_kernel,
                         cudaFuncAttributeMaxDynamicSharedMemorySize, FUSED_SMEM);
    fused_conv_kernel<<<dim3(NTILE * NSTRIP, BATCH), 256, FUSED_SMEM>>>(
        c1w, c1b, c2w, c2b, value);
    combine_kernel<<<15, 256>>>(out);
}

// round 5
// speedup vs baseline: 1.5324x; 1.5324x over previous
#include <cuda_runtime.h>
#include <math.h>

#define BATCH 4
#define PP 900
#define DM 512
#define HH 8
#define DK 64
#define SIDE 30
#define C1 32
#define MP (BATCH*PP)

// padded image layout: logical (p,w) -> padded [p+1][w+1], guards zeroed
#define PW 904
#define PR 902
#define IMG (PR*PW)          // 815408 floats per image
#define NIMG_S (BATCH*HH)    // 32 score images
#define NIMG_C (BATCH*C1)    // 128 conv1-output images

typedef unsigned long long u64;

__device__ __forceinline__ u64 pack2(float a, float b) {
    u64 r; asm("mov.b64 %0, {%1,%2};" : "=l"(r) : "f"(a), "f"(b)); return r;
}
__device__ __forceinline__ u64 ffma2(u64 a, u64 b, u64 c) {
    u64 d; asm("fma.rn.f32x2 %0, %1, %2, %3;" : "=l"(d) : "l"(a), "l"(b), "l"(c)); return d;
}
__device__ __forceinline__ float2 unpack2(u64 v) {
    float2 f; asm("mov.b64 {%0,%1}, %2;" : "=f"(f.x), "=f"(f.y) : "l"(v)); return f;
}

__device__ __align__(128) float g_q[MP * DM];
__device__ __align__(128) float g_k[MP * DM];
__device__ __align__(128) float g_scores[NIMG_S * IMG];  // padded
__device__ __align__(128) float g_c1[NIMG_C * IMG];      // padded
__device__ __align__(128) int   g_idx[NIMG_S * PP];

// ---------------- zero the guard cells of all padded images ----------------
__global__ __launch_bounds__(256) void guard_zero_kernel()
{
    const int img = blockIdx.x;   // 0..159
    float* base = (img < NIMG_S) ? (g_scores + (size_t)img * IMG)
                                 : (g_c1 + (size_t)(img - NIMG_S) * IMG);
    const int t = threadIdx.x;
    // rows 0 and 901 full
    for (int i = t; i < PW; i += 256) {
        base[i] = 0.f;
        base[(size_t)(PR - 1) * PW + i] = 0.f;
    }
    // cols 0, 901, 902, 903 for rows 1..900
    for (int i = t; i < 900 * 4; i += 256) {
        int r = 1 + (i >> 2);
        int c = i & 3;
        int col = (c == 0) ? 0 : (900 + c);
        base[(size_t)r * PW + col] = 0.f;
    }
}

// ---------------- projection GEMM: C = A @ W^T + bias ----------------------
__global__ __launch_bounds__(256) void proj_gemm_kernel(
    const float* __restrict__ A, const float* __restrict__ Wm,
    const float* __restrict__ bias, int which)
{
    float* C = which ? g_k : g_q;
    __shared__ __align__(16) float As[16][132];
    __shared__ __align__(16) float Bs[16][132];
    const int t  = threadIdx.x;
    const int m0 = blockIdx.y * 128;
    const int n0 = blockIdx.x * 128;
    const int lr = t >> 2;
    const int lc = (t & 3) << 2;
    const int ty = t >> 4, tx = t & 15;
    u64 acc[8][4];
    #pragma unroll
    for (int i = 0; i < 8; i++)
        #pragma unroll
        for (int j = 0; j < 4; j++) acc[i][j] = 0ull;

    for (int k0 = 0; k0 < DM; k0 += 16) {
        int ar0 = m0 + lr, ar1 = m0 + lr + 64;
        float4 a0 = make_float4(0.f,0.f,0.f,0.f), a1 = a0;
        if (ar0 < MP) a0 = *(const float4*)(A + (size_t)ar0 * DM + k0 + lc);
        if (ar1 < MP) a1 = *(const float4*)(A + (size_t)ar1 * DM + k0 + lc);
        float4 b0 = *(const float4*)(Wm + (size_t)(n0 + lr)      * DM + k0 + lc);
        float4 b1 = *(const float4*)(Wm + (size_t)(n0 + lr + 64) * DM + k0 + lc);
        if (k0) __syncthreads();
        As[lc+0][lr] = a0.x; As[lc+1][lr] = a0.y; As[lc+2][lr] = a0.z; As[lc+3][lr] = a0.w;
        As[lc+0][lr+64] = a1.x; As[lc+1][lr+64] = a1.y; As[lc+2][lr+64] = a1.z; As[lc+3][lr+64] = a1.w;
        Bs[lc+0][lr] = b0.x; Bs[lc+1][lr] = b0.y; Bs[lc+2][lr] = b0.z; Bs[lc+3][lr] = b0.w;
        Bs[lc+0][lr+64] = b1.x; Bs[lc+1][lr+64] = b1.y; Bs[lc+2][lr+64] = b1.z; Bs[lc+3][lr+64] = b1.w;
        __syncthreads();
        #pragma unroll
        for (int kk = 0; kk < 16; kk++) {
            float a[8];
            *(float4*)&a[0] = *(const float4*)&As[kk][ty*8];
            *(float4*)&a[4] = *(const float4*)&As[kk][ty*8+4];
            ulonglong2 B0 = *(const ulonglong2*)&Bs[kk][tx*8];
            ulonglong2 B1 = *(const ulonglong2*)&Bs[kk][tx*8+4];
            #pragma unroll
            for (int i = 0; i < 8; i++) {
                u64 aa = pack2(a[i], a[i]);
                acc[i][0] = ffma2(aa, B0.x, acc[i][0]);
                acc[i][1] = ffma2(aa, B0.y, acc[i][1]);
                acc[i][2] = ffma2(aa, B1.x, acc[i][2]);
                acc[i][3] = ffma2(aa, B1.y, acc[i][3]);
            }
        }
    }
    const int c0 = n0 + tx * 8;
    float bi[8];
    #pragma unroll
    for (int j = 0; j < 8; j++) bi[j] = bias[c0 + j];
    #pragma unroll
    for (int i = 0; i < 8; i++) {
        int r = m0 + ty * 8 + i;
        if (r >= MP) continue;
        float* cp = C + (size_t)r * DM + c0;
        #pragma unroll
        for (int j = 0; j < 4; j++) {
            float2 f = unpack2(acc[i][j]);
            cp[j*2+0] = f.x + bi[j*2+0];
            cp[j*2+1] = f.y + bi[j*2+1];
        }
    }
}

// -------- batched scores GEMM: scores[b,h] = Qh @ Kh^T (padded output) -----
__global__ __launch_bounds__(256) void scores_gemm_kernel()
{
    const int z = blockIdx.z;
    const int b = z >> 3, h = z & 7;
    const float* A  = g_q + (size_t)b * PP * DM + h * DK;
    const float* Bm = g_k + (size_t)b * PP * DM + h * DK;
    float* C = g_scores + (size_t)z * IMG;

    __shared__ __align__(16) float As[16][132];
    __shared__ __align__(16) float Bs[16][132];
    const int t  = threadIdx.x;
    const int m0 = blockIdx.y * 128;
    const int n0 = blockIdx.x * 128;
    const int lr = t >> 2;
    const int lc = (t & 3) << 2;
    const int ty = t >> 4, tx = t & 15;
    u64 acc[8][4];
    #pragma unroll
    for (int i = 0; i < 8; i++)
        #pragma unroll
        for (int j = 0; j < 4; j++) acc[i][j] = 0ull;

    for (int k0 = 0; k0 < DK; k0 += 16) {
        int ar0 = m0 + lr, ar1 = m0 + lr + 64;
        int br0 = n0 + lr, br1 = n0 + lr + 64;
        float4 a0 = make_float4(0.f,0.f,0.f,0.f), a1 = a0, b0 = a0, b1 = a0;
        if (ar0 < PP) a0 = *(const float4*)(A  + (size_t)ar0 * DM + k0 + lc);
        if (ar1 < PP) a1 = *(const float4*)(A  + (size_t)ar1 * DM + k0 + lc);
        if (br0 < PP) b0 = *(const float4*)(Bm + (size_t)br0 * DM + k0 + lc);
        if (br1 < PP) b1 = *(const float4*)(Bm + (size_t)br1 * DM + k0 + lc);
        if (k0) __syncthreads();
        As[lc+0][lr] = a0.x; As[lc+1][lr] = a0.y; As[lc+2][lr] = a0.z; As[lc+3][lr] = a0.w;
        As[lc+0][lr+64] = a1.x; As[lc+1][lr+64] = a1.y; As[lc+2][lr+64] = a1.z; As[lc+3][lr+64] = a1.w;
        Bs[lc+0][lr] = b0.x; Bs[lc+1][lr] = b0.y; Bs[lc+2][lr] = b0.z; Bs[lc+3][lr] = b0.w;
        Bs[lc+0][lr+64] = b1.x; Bs[lc+1][lr+64] = b1.y; Bs[lc+2][lr+64] = b1.z; Bs[lc+3][lr+64] = b1.w;
        __syncthreads();
        #pragma unroll
        for (int kk = 0; kk < 16; kk++) {
            float a[8];
            *(float4*)&a[0] = *(const float4*)&As[kk][ty*8];
            *(float4*)&a[4] = *(const float4*)&As[kk][ty*8+4];
            ulonglong2 B0 = *(const ulonglong2*)&Bs[kk][tx*8];
            ulonglong2 B1 = *(const ulonglong2*)&Bs[kk][tx*8+4];
            #pragma unroll
            for (int i = 0; i < 8; i++) {
                u64 aa = pack2(a[i], a[i]);
                acc[i][0] = ffma2(aa, B0.x, acc[i][0]);
                acc[i][1] = ffma2(aa, B0.y, acc[i][1]);
                acc[i][2] = ffma2(aa, B1.x, acc[i][2]);
                acc[i][3] = ffma2(aa, B1.y, acc[i][3]);
            }
        }
    }
    const int c0 = n0 + tx * 8;
    #pragma unroll
    for (int i = 0; i < 8; i++) {
        int r = m0 + ty * 8 + i;
        if (r >= PP) continue;
        float* cp = C + (size_t)(r + 1) * PW + 1;   // padded row, col offset 1
        #pragma unroll
        for (int j = 0; j < 4; j++) {
            float2 f = unpack2(acc[i][j]);
            int c = c0 + j * 2;
            if (c     < PP) cp[c]     = f.x;
            if (c + 1 < PP) cp[c + 1] = f.y;
        }
    }
}

// ---------------- column argmax over p for each (bh, w) --------------------
__global__ __launch_bounds__(256) void argmax_kernel()
{
    const int w  = blockIdx.x * 256 + threadIdx.x;
    const int bh = blockIdx.y;
    if (w >= PP) return;
    const float* base = g_scores + (size_t)bh * IMG + PW + 1 + w;
    float best = base[0];
    int   bi = 0;
    int p = 1;
    for (; p + 15 < PP; p += 16) {
        float v[16];
        #pragma unroll
        for (int u = 0; u < 16; u++) v[u] = base[(size_t)(p + u) * PW];
        #pragma unroll
        for (int u = 0; u < 16; u++)
            if (v[u] > best) { best = v[u]; bi = p + u; }
    }
    for (; p < PP; p++) {
        float v = base[(size_t)p * PW];
        if (v > best) { best = v; bi = p; }
    }
    g_idx[bh * PP + w] = bi;
}

// -------- gaussian (table) + scale + softmax (in-place, padded) ------------
__global__ __launch_bounds__(256) void gauss_softmax_kernel()
{
    const int p  = blockIdx.x;
    const int bh = blockIdx.y;
    float* row = g_scores + (size_t)bh * IMG + (size_t)(p + 1) * PW + 1;
    const int* idxr = g_idx + bh * PP;
    const int t = threadIdx.x;
    const float ys0 = -1.0f + (2.0f / 29.0f) * (float)(p / SIDE);
    const float xs0 = -1.0f + (2.0f / 29.0f) * (float)(p % SIDE);

    __shared__ float gx[SIDE], gy[SIDE], sh[32];
    if (t < SIDE) {
        float d = xs0 - (float)t;
        gx[t] = __expf(-d * d * (1.0f / 50.0f));
    } else if (t >= 32 && t < 32 + SIDE) {
        float d = ys0 - (float)(t - 32);
        gy[t - 32] = __expf(-d * d * (1.0f / 50.0f));
    }
    __syncthreads();

    float v[4];
    float m = -3.0e38f;
    #pragma unroll
    for (int i = 0; i < 4; i++) {
        int w = t + i * 256;
        v[i] = -3.0e38f;
        if (w < PP) {
            int id = idxr[w];
            int iy = id / SIDE;
            int ix = id - iy * SIDE;
            float g = gx[ix] * gy[iy];
            v[i] = g * row[w] * 0.125f;
            m = fmaxf(m, v[i]);
        }
    }
    #pragma unroll
    for (int off = 16; off; off >>= 1) m = fmaxf(m, __shfl_xor_sync(0xffffffffu, m, off));
    if ((t & 31) == 0) sh[t >> 5] = m;
    __syncthreads();
    if (t < 32) {
        float x = (t < 8) ? sh[t] : -3.0e38f;
        #pragma unroll
        for (int off = 4; off; off >>= 1) x = fmaxf(x, __shfl_xor_sync(0xffffffffu, x, off));
        if (t == 0) sh[0] = x;
    }
    __syncthreads();
    m = sh[0];
    __syncthreads();

    float e[4];
    float s = 0.f;
    #pragma unroll
    for (int i = 0; i < 4; i++) {
        int w = t + i * 256;
        e[i] = 0.f;
        if (w < PP) { e[i] = __expf(v[i] - m); s += e[i]; }
    }
    #pragma unroll
    for (int off = 16; off; off >>= 1) s += __shfl_xor_sync(0xffffffffu, s, off);
    if ((t & 31) == 0) sh[t >> 5] = s;
    __syncthreads();
    if (t < 32) {
        float x = (t < 8) ? sh[t] : 0.f;
        #pragma unroll
        for (int off = 4; off; off >>= 1) x += __shfl_xor_sync(0xffffffffu, x, off);
        if (t == 0) sh[0] = x;
    }
    __syncthreads();
    float inv = 1.0f / sh[0];
    #pragma unroll
    for (int i = 0; i < 4; i++) {
        int w = t + i * 256;
        if (w < PP) row[w] = e[i] * inv;
    }
}

// ---------------- conv1 (8->32 ch) + bias + relu, guard-padded -------------
// block (p, b); thread: ocg = 4 oc-pairs, chunk of 4 contiguous w; no predicates.
__global__ __launch_bounds__(256) void conv1_kernel(
    const float* __restrict__ w1, const float* __restrict__ b1)
{
    const int p = blockIdx.x;
    const int b = blockIdx.y;
    __shared__ u64 wsm[8 * 9 * 16];
    for (int i = threadIdx.x; i < 8 * 9 * 16; i += 256) {
        int op  = i & 3;
        int og  = (i >> 2) & 3;
        int rest = i >> 4;
        int ci  = rest / 9;
        int dydx = rest - ci * 9;
        int oc0 = og * 8 + op * 2;
        wsm[i] = pack2(w1[(oc0 * 8 + ci) * 9 + dydx],
                       w1[((oc0 + 1) * 8 + ci) * 9 + dydx]);
    }
    __syncthreads();

    const int ocg  = threadIdx.x >> 6;
    const int slot = threadIdx.x & 63;
    const float* attn = g_scores + (size_t)b * HH * IMG;

    u64 bia[4];
    #pragma unroll
    for (int op = 0; op < 4; op++)
        bia[op] = pack2(b1[ocg * 8 + op * 2], b1[ocg * 8 + op * 2 + 1]);

    #pragma unroll 1
    for (int j = 0; j < 4; j++) {
        const int c = slot + 64 * j;       // 0..255, active < 225
        if (c >= 225) continue;
        // padded cols 4c..4c+5 cover logical w-1..w+4 for w0 = 4c (logical)
        u64 acc[4][4];
        #pragma unroll
        for (int k = 0; k < 4; k++)
            #pragma unroll
            for (int op = 0; op < 4; op++) acc[k][op] = bia[op];

        #pragma unroll 1
        for (int ci = 0; ci < 8; ci++) {
            // padded rows p, p+1, p+2 (guards give SAME padding)
            const float* ip = attn + (size_t)ci * IMG + (size_t)p * PW + 4 * c;
            float4 r0a = *(const float4*)ip;
            float2 r0b = *(const float2*)(ip + 4);
            float4 r1a = *(const float4*)(ip + PW);
            float2 r1b = *(const float2*)(ip + PW + 4);
            float4 r2a = *(const float4*)(ip + 2 * PW);
            float2 r2b = *(const float2*)(ip + 2 * PW + 4);
            float vr[3][6] = {
                {r0a.x, r0a.y, r0a.z, r0a.w, r0b.x, r0b.y},
                {r1a.x, r1a.y, r1a.z, r1a.w, r1b.x, r1b.y},
                {r2a.x, r2a.y, r2a.z, r2a.w, r2b.x, r2b.y}};
            #pragma unroll
            for (int dy = 0; dy < 3; dy++) {
                u64 in2[6];
                #pragma unroll
                for (int m = 0; m < 6; m++) in2[m] = pack2(vr[dy][m], vr[dy][m]);
                const u64* wb = &wsm[(ci * 9 + dy * 3) * 16 + ocg * 4];
                #pragma unroll
                for (int dx = 0; dx < 3; dx++) {
                    u64 wp0 = wb[dx * 16 + 0];
                    u64 wp1 = wb[dx * 16 + 1];
                    u64 wp2 = wb[dx * 16 + 2];
                    u64 wp3 = wb[dx * 16 + 3];
                    #pragma unroll
                    for (int k = 0; k < 4; k++) {
                        acc[k][0] = ffma2(in2[k + dx], wp0, acc[k][0]);
                        acc[k][1] = ffma2(in2[k + dx], wp1, acc[k][1]);
                        acc[k][2] = ffma2(in2[k + dx], wp2, acc[k][2]);
                        acc[k][3] = ffma2(in2[k + dx], wp3, acc[k][3]);
                    }
                }
            }
        }
        // store: padded (p+1, 4c+1..4c+4) per oc
        size_t outb = ((size_t)(b * C1 + ocg * 8)) * IMG + (size_t)(p + 1) * PW + 4 * c + 1;
        #pragma unroll
        for (int op = 0; op < 4; op++) {
            float* d0 = g_c1 + outb + (size_t)(op * 2)     * IMG;
            float* d1 = g_c1 + outb + (size_t)(op * 2 + 1) * IMG;
            float2 f0 = unpack2(acc[0][op]);
            float2 f1 = unpack2(acc[1][op]);
            float2 f2 = unpack2(acc[2][op]);
            float2 f3 = unpack2(acc[3][op]);
            d0[0] = fmaxf(f0.x, 0.f); d0[1] = fmaxf(f1.x, 0.f);
            d0[2] = fmaxf(f2.x, 0.f); d0[3] = fmaxf(f3.x, 0.f);
            d1[0] = fmaxf(f0.y, 0.f); d1[1] = fmaxf(f1.y, 0.f);
            d1[2] = fmaxf(f2.y, 0.f); d1[3] = fmaxf(f3.y, 0.f);
        }
    }
}

// ------- conv2 (32->8) + bias + relu + value-dot + head-mean, padded -------
__global__ __launch_bounds__(256) void conv2_reduce_kernel(
    const float* __restrict__ w2, const float* __restrict__ b2,
    const float* __restrict__ value, float* __restrict__ out)
{
    const int p = blockIdx.x;
    const int b = blockIdx.y;
    __shared__ u64 wsm[32 * 9 * 4];
    for (int i = threadIdx.x; i < 32 * 9 * 4; i += 256) {
        int op = i & 3;
        int rest = i >> 2;
        int ci = rest / 9;
        int dydx = rest - ci * 9;
        wsm[i] = pack2(w2[(op * 2 * 32 + ci) * 9 + dydx],
                       w2[((op * 2 + 1) * 32 + ci) * 9 + dydx]);
    }
    __syncthreads();

    const int t = threadIdx.x;
    const bool active = (t < 225);
    const float* inb = g_c1 + (size_t)b * C1 * IMG;

    u64 acc[4][4];
    #pragma unroll
    for (int k = 0; k < 4; k++)
        #pragma unroll
        for (int op = 0; op < 4; op++)
            acc[k][op] = pack2(b2[op * 2], b2[op * 2 + 1]);

    if (active) {
        #pragma unroll 1
        for (int ci = 0; ci < C1; ci++) {
            const float* ip = inb + (size_t)ci * IMG + (size_t)p * PW + 4 * t;
            float4 r0a = *(const float4*)ip;
            float2 r0b = *(const float2*)(ip + 4);
            float4 r1a = *(const float4*)(ip + PW);
            float2 r1b = *(const float2*)(ip + PW + 4);
            float4 r2a = *(const float4*)(ip + 2 * PW);
            float2 r2b = *(const float2*)(ip + 2 * PW + 4);
            float vr[3][6] = {
                {r0a.x, r0a.y, r0a.z, r0a.w, r0b.x, r0b.y},
                {r1a.x, r1a.y, r1a.z, r1a.w, r1b.x, r1b.y},
                {r2a.x, r2a.y, r2a.z, r2a.w, r2b.x, r2b.y}};
            #pragma unroll
            for (int dy = 0; dy < 3; dy++) {
                u64 in2[6];
                #pragma unroll
                for (int m = 0; m < 6; m++) in2[m] = pack2(vr[dy][m], vr[dy][m]);
                const u64* wb = &wsm[(ci * 9 + dy * 3) * 4];
                #pragma unroll
                for (int dx = 0; dx < 3; dx++) {
                    u64 p0 = wb[dx * 4 + 0];
                    u64 p1 = wb[dx * 4 + 1];
                    u64 p2 = wb[dx * 4 + 2];
                    u64 p3 = wb[dx * 4 + 3];
                    #pragma unroll
                    for (int k = 0; k < 4; k++) {
                        acc[k][0] = ffma2(in2[k + dx], p0, acc[k][0]);
                        acc[k][1] = ffma2(in2[k + dx], p1, acc[k][1]);
                        acc[k][2] = ffma2(in2[k + dx], p2, acc[k][2]);
                        acc[k][3] = ffma2(in2[k + dx], p3, acc[k][3]);
                    }
                }
            }
        }
    }

    float part = 0.f;
    if (active) {
        float4 vv = *(const float4*)(value + b * PP + 4 * t);
        float val[4] = {vv.x, vv.y, vv.z, vv.w};
        #pragma unroll
        for (int k = 0; k < 4; k++) {
            float s = 0.f;
            #pragma unroll
            for (int op = 0; op < 4; op++) {
                float2 f = unpack2(acc[k][op]);
                s += fmaxf(f.x, 0.f) + fmaxf(f.y, 0.f);
            }
            part += s * val[k];
        }
    }
    __shared__ float sh[32];
    #pragma unroll
    for (int off = 16; off; off >>= 1) part += __shfl_xor_sync(0xffffffffu, part, off);
    if ((t & 31) == 0) sh[t >> 5] = part;
    __syncthreads();
    if (t < 32) {
        float x = (t < 8) ? sh[t] : 0.f;
        #pragma unroll
        for (int off = 4; off; off >>= 1) x += __shfl_xor_sync(0xffffffffu, x, off);
        if (t == 0) out[b * PP + p] = x * 0.125f;
    }
}

// ---------------------------------------------------------------------------
extern "C" void kernel_launch(void* const* d_in, const int* in_sizes, int n_in,
                              void* d_out, int out_size)
{
    const float* query = (const float*)d_in[0];
    const float* key_t = (const float*)d_in[1];
    const float* value = (const float*)d_in[2];
    const float* Wq    = (const float*)d_in[3];
    const float* bq    = (const float*)d_in[4];
    const float* Wk    = (const float*)d_in[5];
    const float* bk    = (const float*)d_in[6];
    const float* c1w   = (const float*)d_in[7];
    const float* c1b   = (const float*)d_in[8];
    const float* c2w   = (const float*)d_in[9];
    const float* c2b   = (const float*)d_in[10];
    float* out = (float*)d_out;
    (void)in_sizes; (void)n_in; (void)out_size;

    guard_zero_kernel<<<NIMG_S + NIMG_C, 256>>>();
    proj_gemm_kernel<<<dim3(4, 29), 256>>>(query, Wq, bq, 0);
    proj_gemm_kernel<<<dim3(4, 29), 256>>>(key_t, Wk, bk, 1);
    scores_gemm_kernel<<<dim3(8, 8, 32), 256>>>();
    argmax_kernel<<<dim3(4, 32), 256>>>();
    gauss_softmax_kernel<<<dim3(900, 32), 256>>>();
    conv1_kernel<<<dim3(900, 4), 256>>>(c1w, c1b);
    conv2_reduce_kernel<<<dim3(900, 4), 256>>>(c2w, c2b, value, out);
}